// round 9
// baseline (speedup 1.0000x reference)
#include <cuda_runtime.h>

// Fixed problem shape.
#define BB 8
#define QQ 900
#define KK 1203
#define NN 100
#define RPB 10                    // rows per block (10 | 900 -> no batch straddle)
#define THREADS (RPB * 32)        // 320, warp w handles row q0+w
#define BLKX (QQ / RPB)           // 90

// cost[b,q,n] = 2*focal_cls + 5*L1 - 2*GIoU
// Gather design with per-batch LABEL SORTING: each block rank-sorts the 100
// labels of its batch in smem, gathers logits in ascending-address order
// (cuts divergent L1tex wavefronts ~2x), and scatter-stores results through
// the permutation.
__global__ void __launch_bounds__(THREADS) matcher_cost_kernel(
    const float*  __restrict__ logits,   // (B,Q,K)
    const float4* __restrict__ pboxes,   // (B,Q,4)
    const int*    __restrict__ labels,   // (B,N)
    const float4* __restrict__ tboxes,   // (B,N,4)
    float* __restrict__ out)             // (B,Q,N)
{
    __shared__ int    s_raw[NN];     // raw labels
    __shared__ int    s_slab[NN];    // sorted clamped labels
    __shared__ int    s_perm[NN];    // rank -> original n
    __shared__ float4 s_tb[NN];      // tboxes permuted to sorted order

    const int b    = blockIdx.y;
    const int tid  = threadIdx.x;
    const int w    = tid >> 5;
    const int lane = tid & 31;

    // ---- per-batch label rank-sort (once per block) ----
    if (tid < NN) s_raw[tid] = labels[b * NN + tid];
    __syncthreads();
    if (tid < NN) {
        const int myl = s_raw[tid];
        int rank = 0;
        #pragma unroll 4
        for (int i = 0; i < NN; i++) {
            int li = s_raw[i];
            rank += (li < myl) | ((li == myl) & (i < tid));
        }
        s_slab[rank] = min(max(myl, 0), KK - 1);
        s_perm[rank] = tid;
        s_tb[rank]   = tboxes[b * NN + tid];
    }
    __syncthreads();

    // ---- each warp: one row, 100 outputs in sorted-label order ----
    const int q   = blockIdx.x * RPB + w;
    const long row = (long)b * QQ + q;
    const float* lrow = logits + row * KK;

    // Front-batched gathers: ascending addresses within each round.
    float xv[4];
    #pragma unroll
    for (int i = 0; i < 4; i++) {
        int j  = lane + i * 32;
        int jj = min(j, NN - 1);            // masked lanes duplicate last (L1 hit)
        xv[i] = __ldg(lrow + s_slab[jj]);
    }

    const float4 pb = pboxes[row];
    const float px0 = pb.x - 0.5f * pb.z, px1 = pb.x + 0.5f * pb.z;
    const float py0 = pb.y - 0.5f * pb.w, py1 = pb.y + 0.5f * pb.w;
    const float area1 = pb.z * pb.w;
    float* const orow = out + row * NN;

    #pragma unroll
    for (int i = 0; i < 4; i++) {
        int j = lane + i * 32;
        if (j < NN) {
            float x = xv[i];

            // focal class cost (3 MUFU)
            float e  = __expf(-x);
            float sg = 1.0f + e;
            float p  = __fdividef(1.0f, sg);
            float L  = __logf(sg);
            float logp   = fmaxf(-L,     -18.420681f);
            float log1mp = fmaxf(-x - L, -18.420681f);
            float omp = 1.0f - p;
            float cls = -0.25f * omp * omp * logp + 0.75f * p * p * log1mp;

            // L1 box cost
            float4 tb = s_tb[j];
            float l1 = fabsf(pb.x - tb.x) + fabsf(pb.y - tb.y)
                     + fabsf(pb.z - tb.z) + fabsf(pb.w - tb.w);

            // GIoU (1 MUFU)
            float tx0 = tb.x - 0.5f * tb.z, tx1 = tb.x + 0.5f * tb.z;
            float ty0 = tb.y - 0.5f * tb.w, ty1 = tb.y + 0.5f * tb.w;
            float area2 = tb.z * tb.w;
            float wi = fmaxf(fminf(px1, tx1) - fmaxf(px0, tx0), 0.0f);
            float hi = fmaxf(fminf(py1, ty1) - fmaxf(py0, ty0), 0.0f);
            float inter = wi * hi;
            float uni   = area1 + area2 - inter;
            float wc = fmaxf(px1, tx1) - fminf(px0, tx0);
            float hc = fmaxf(py1, ty1) - fminf(py0, ty0);
            float ac = wc * hc;
            float num  = ac * (inter - uni) + uni * uni;
            float giou = num * __fdividef(1.0f, uni * ac);

            // scatter through permutation (within one 400B row -> ~4 lines)
            orow[s_perm[j]] = 2.0f * cls + 5.0f * l1 - 2.0f * giou;
        }
    }
}

extern "C" void kernel_launch(void* const* d_in, const int* in_sizes, int n_in,
                              void* d_out, int out_size)
{
    const float*  logits = (const float*)d_in[0];
    const float4* pboxes = (const float4*)d_in[1];
    const int*    labels = (const int*)d_in[2];
    const float4* tboxes = (const float4*)d_in[3];
    float* out = (float*)d_out;

    dim3 grid(BLKX, BB);   // (90, 8) = 720 blocks, 10 warps each, 1 row/warp
    matcher_cost_kernel<<<grid, THREADS>>>(logits, pboxes, labels, tboxes, out);
}

// round 10
// speedup vs baseline: 1.0409x; 1.0409x over previous
#include <cuda_runtime.h>

// Fixed problem shape.
#define BB 8
#define QQ 900
#define KK 1203
#define NN 100
#define RPB 50                    // rows per block (50*18 = 900)
#define BLKX (QQ / RPB)           // 18
#define WARPS 16
#define THREADS (WARPS * 32)      // 512

// cost[b,q,n] = 2*focal_cls + 5*L1 - 2*GIoU
// Sorted gather: block rank-sorts its batch's 100 labels ONCE (amortized over
// 50 rows), gathers logits in ascending-address order (fewer divergent L1tex
// wavefronts), scatter-stores through the permutation.
__global__ void __launch_bounds__(THREADS) matcher_cost_kernel(
    const float*  __restrict__ logits,   // (B,Q,K)
    const float4* __restrict__ pboxes,   // (B,Q,4)
    const int*    __restrict__ labels,   // (B,N)
    const float4* __restrict__ tboxes,   // (B,N,4)
    float* __restrict__ out)             // (B,Q,N)
{
    __shared__ int    s_raw[NN];     // raw labels
    __shared__ int    s_slab[NN];    // sorted clamped labels
    __shared__ int    s_perm[NN];    // rank -> original n
    __shared__ float4 s_tb[NN];      // tboxes in sorted order

    const int b    = blockIdx.y;
    const int tid  = threadIdx.x;
    const int w    = tid >> 5;
    const int lane = tid & 31;

    // ---- per-block label rank-sort (once, amortized over 50 rows) ----
    if (tid < NN) s_raw[tid] = labels[b * NN + tid];
    __syncthreads();
    if (tid < NN) {
        const int myl = s_raw[tid];
        int rank = 0;
        #pragma unroll 4
        for (int i = 0; i < NN; i++) {
            int li = s_raw[i];
            rank += (li < myl) | ((li == myl) & (i < tid));
        }
        s_slab[rank] = min(max(myl, 0), KK - 1);
        s_perm[rank] = tid;
        s_tb[rank]   = tboxes[b * NN + tid];
    }
    __syncthreads();   // only block-wide barrier

    const int q0 = blockIdx.x * RPB;

    // warp w handles rows q0+w, q0+w+16, q0+w+32 (while < q0+50)
    #pragma unroll 1
    for (int rq = w; rq < RPB; rq += WARPS) {
        const long row = (long)b * QQ + (q0 + rq);
        const float* lrow = logits + row * KK;

        // front-batched gathers, ascending addresses per round
        float xv[4];
        #pragma unroll
        for (int i = 0; i < 4; i++) {
            int j  = lane + i * 32;
            int jj = min(j, NN - 1);
            xv[i] = __ldg(lrow + s_slab[jj]);
        }

        const float4 pb = pboxes[row];
        const float px0 = pb.x - 0.5f * pb.z, px1 = pb.x + 0.5f * pb.z;
        const float py0 = pb.y - 0.5f * pb.w, py1 = pb.y + 0.5f * pb.w;
        const float area1 = pb.z * pb.w;
        float* const orow = out + row * NN;

        #pragma unroll
        for (int i = 0; i < 4; i++) {
            int j = lane + i * 32;
            if (j < NN) {
                float x = xv[i];

                // focal class cost (3 MUFU)
                float e  = __expf(-x);
                float sg = 1.0f + e;
                float p  = __fdividef(1.0f, sg);
                float L  = __logf(sg);
                float logp   = fmaxf(-L,     -18.420681f);
                float log1mp = fmaxf(-x - L, -18.420681f);
                float omp = 1.0f - p;
                float cls = -0.25f * omp * omp * logp + 0.75f * p * p * log1mp;

                // L1 box cost
                float4 tb = s_tb[j];
                float l1 = fabsf(pb.x - tb.x) + fabsf(pb.y - tb.y)
                         + fabsf(pb.z - tb.z) + fabsf(pb.w - tb.w);

                // GIoU (1 MUFU)
                float tx0 = tb.x - 0.5f * tb.z, tx1 = tb.x + 0.5f * tb.z;
                float ty0 = tb.y - 0.5f * tb.w, ty1 = tb.y + 0.5f * tb.w;
                float area2 = tb.z * tb.w;
                float wi = fmaxf(fminf(px1, tx1) - fmaxf(px0, tx0), 0.0f);
                float hi = fmaxf(fminf(py1, ty1) - fmaxf(py0, ty0), 0.0f);
                float inter = wi * hi;
                float uni   = area1 + area2 - inter;
                float wc = fmaxf(px1, tx1) - fminf(px0, tx0);
                float hc = fmaxf(py1, ty1) - fminf(py0, ty0);
                float ac = wc * hc;
                float num  = ac * (inter - uni) + uni * uni;
                float giou = num * __fdividef(1.0f, uni * ac);

                // scatter within this row's 400B range
                orow[s_perm[j]] = 2.0f * cls + 5.0f * l1 - 2.0f * giou;
            }
        }
    }
}

extern "C" void kernel_launch(void* const* d_in, const int* in_sizes, int n_in,
                              void* d_out, int out_size)
{
    const float*  logits = (const float*)d_in[0];
    const float4* pboxes = (const float4*)d_in[1];
    const int*    labels = (const int*)d_in[2];
    const float4* tboxes = (const float4*)d_in[3];
    float* out = (float*)d_out;

    dim3 grid(BLKX, BB);   // (18, 8) = 144 blocks, 16 warps, 50 rows/block
    matcher_cost_kernel<<<grid, THREADS>>>(logits, pboxes, labels, tboxes, out);
}

// round 11
// speedup vs baseline: 1.5018x; 1.4428x over previous
#include <cuda_runtime.h>

// Fixed problem shape.
#define BB 8
#define QQ 900
#define KK 1203
#define NN 100
#define NQUAD (NN / 4)                    // 25
#define HALFQ (QQ / 2)                    // 450 row-pairs per batch
#define TOTALT (BB * HALFQ * NQUAD)       // 90000 threads, 8 outputs each

// cost[b,q,n] = 2*focal_cls + 5*L1 - 2*GIoU
// One thread: the same n-quad of TWO adjacent rows (2r, 2r+1) of one batch.
// Labels + target boxes are shared between the rows -> loaded once per 8
// outputs; 8 independent logits gathers in flight per thread.
__global__ void __launch_bounds__(128) matcher_cost_kernel(
    const float*  __restrict__ logits,   // (B,Q,K)
    const float4* __restrict__ pboxes,   // (B,Q,4)
    const int4*   __restrict__ labels4,  // (B,N) as int4
    const float4* __restrict__ tboxes,   // (B,N,4)
    float4* __restrict__ out4)           // (B,Q,N) as float4
{
    int gid = blockIdx.x * blockDim.x + threadIdx.x;
    if (gid >= TOTALT) return;

    const int quad  = gid % NQUAD;        // n-quad index
    const int pidx  = gid / NQUAD;        // pair index (b*450 + r)
    const int b     = pidx / HALFQ;
    const int r     = pidx - b * HALFQ;
    const int q0    = 2 * r;
    const long bq0  = (long)b * QQ + q0;  // first row

    // ---- shared-per-pair loads ----
    int4 lab4 = __ldg(labels4 + b * NQUAD + quad);
    const int l0 = min(max(lab4.x, 0), KK - 1);
    const int l1i = min(max(lab4.y, 0), KK - 1);
    const int l2 = min(max(lab4.z, 0), KK - 1);
    const int l3 = min(max(lab4.w, 0), KK - 1);

    const float* lrowA = logits + bq0 * KK;
    const float* lrowB = lrowA + KK;

    // 8 independent gathers, front-batched (warm L2 across graph replays)
    float a0 = __ldg(lrowA + l0), a1 = __ldg(lrowA + l1i);
    float a2 = __ldg(lrowA + l2), a3 = __ldg(lrowA + l3);
    float c0 = __ldg(lrowB + l0), c1 = __ldg(lrowB + l1i);
    float c2 = __ldg(lrowB + l2), c3 = __ldg(lrowB + l3);

    const int bn = b * NN + quad * 4;
    float4 tb0 = __ldg(tboxes + bn + 0);
    float4 tb1 = __ldg(tboxes + bn + 1);
    float4 tb2 = __ldg(tboxes + bn + 2);
    float4 tb3 = __ldg(tboxes + bn + 3);

    float4 pbA = __ldg(pboxes + bq0);
    float4 pbB = __ldg(pboxes + bq0 + 1);

    // target xyxy + areas (shared by both rows)
    float txy0[4][4], ta[4];
    {
        float4 tbs[4] = {tb0, tb1, tb2, tb3};
        #pragma unroll
        for (int i = 0; i < 4; i++) {
            txy0[i][0] = tbs[i].x - 0.5f * tbs[i].z;
            txy0[i][1] = tbs[i].y - 0.5f * tbs[i].w;
            txy0[i][2] = tbs[i].x + 0.5f * tbs[i].z;
            txy0[i][3] = tbs[i].y + 0.5f * tbs[i].w;
            ta[i] = tbs[i].z * tbs[i].w;
        }
    }

    float xs[2][4] = {{a0, a1, a2, a3}, {c0, c1, c2, c3}};
    float4 pbs[2] = {pbA, pbB};
    float4 tbs[4] = {tb0, tb1, tb2, tb3};

    #pragma unroll
    for (int rr = 0; rr < 2; rr++) {
        const float4 pb = pbs[rr];
        const float px0 = pb.x - 0.5f * pb.z, px1 = pb.x + 0.5f * pb.z;
        const float py0 = pb.y - 0.5f * pb.w, py1 = pb.y + 0.5f * pb.w;
        const float area1 = pb.z * pb.w;

        float4 res;
        float* resp = &res.x;

        #pragma unroll
        for (int i = 0; i < 4; i++) {
            float x = xs[rr][i];

            // focal class cost (3 MUFU)
            float e  = __expf(-x);
            float sg = 1.0f + e;
            float p  = __fdividef(1.0f, sg);
            float L  = __logf(sg);
            float logp   = fmaxf(-L,     -18.420681f);
            float log1mp = fmaxf(-x - L, -18.420681f);
            float omp = 1.0f - p;
            float cls = -0.25f * omp * omp * logp + 0.75f * p * p * log1mp;

            // L1 box cost
            float4 tb = tbs[i];
            float l1 = fabsf(pb.x - tb.x) + fabsf(pb.y - tb.y)
                     + fabsf(pb.z - tb.z) + fabsf(pb.w - tb.w);

            // GIoU (1 MUFU)
            float wi = fmaxf(fminf(px1, txy0[i][2]) - fmaxf(px0, txy0[i][0]), 0.0f);
            float hi = fmaxf(fminf(py1, txy0[i][3]) - fmaxf(py0, txy0[i][1]), 0.0f);
            float inter = wi * hi;
            float uni   = area1 + ta[i] - inter;
            float wc = fmaxf(px1, txy0[i][2]) - fminf(px0, txy0[i][0]);
            float hc = fmaxf(py1, txy0[i][3]) - fminf(py0, txy0[i][1]);
            float ac = wc * hc;
            float num  = ac * (inter - uni) + uni * uni;
            float giou = num * __fdividef(1.0f, uni * ac);

            resp[i] = 2.0f * cls + 5.0f * l1 - 2.0f * giou;
        }

        // (bq0+rr)*NN is 16B-aligned: NN=100 -> 25 float4 per row
        out4[(bq0 + rr) * NQUAD + quad] = res;
    }
}

extern "C" void kernel_launch(void* const* d_in, const int* in_sizes, int n_in,
                              void* d_out, int out_size)
{
    const float*  logits  = (const float*)d_in[0];
    const float4* pboxes  = (const float4*)d_in[1];
    const int4*   labels4 = (const int4*)d_in[2];
    const float4* tboxes  = (const float4*)d_in[3];
    float4* out4 = (float4*)d_out;

    const int threads = 128;
    const int blocks  = (TOTALT + threads - 1) / threads;   // 704
    matcher_cost_kernel<<<blocks, threads>>>(logits, pboxes, labels4, tboxes, out4);
}